// round 1
// baseline (speedup 1.0000x reference)
#include <cuda_runtime.h>
#include <cstdint>

#define N_ACT   1500000
#define NB_CONV ((N_ACT + 255) / 256)        // 5860 blocks, 256 rows each
#define NB_ELT  ((N_ACT * 8) / 256)          // 46875: N*32 floats / 4 per thread / 256
#define BN_EPS  1e-5f

// ---------------- scratch (no allocations allowed) ----------------
__device__ float g_h1[(size_t)N_ACT * 32];     // conv1 output -> bn1relu in place
__device__ float g_h2[(size_t)N_ACT * 32];     // conv2 output
__device__ float g_part1[NB_CONV * 64];        // per-block [sum(32), sumsq(32)]
__device__ float g_part2[NB_CONV * 64];
__device__ float g_coef1[64];                  // [a(32), c(32)] : y = a*h + c
__device__ float g_coef2[64];

// ---------------- f32x2 helpers (Blackwell packed fp32) ----------------
__device__ __forceinline__ unsigned long long splat2(float w) {
    unsigned long long r;
    asm("mov.b64 %0, {%1, %1};" : "=l"(r) : "f"(w));
    return r;
}
__device__ __forceinline__ float2 unpack2(unsigned long long v) {
    float2 f;
    asm("mov.b64 {%0, %1}, %2;" : "=f"(f.x), "=f"(f.y) : "l"(v));
    return f;
}
__device__ __forceinline__ void fma2(unsigned long long& acc,
                                     unsigned long long x,
                                     unsigned long long w) {
    asm("fma.rn.f32x2 %0, %1, %2, %0;" : "+l"(acc) : "l"(x), "l"(w));
}

// ---------------- conv: out[i] = sum_k gather(X, idx[k]) @ W[k] ----------------
// Warp tile: 32 rows x 32 cols. lane = output channel; rows packed in f32x2 pairs.
// which==0: X = Xin (harness x), H = g_h1, part = g_part1
// which==1: X = g_h1 (post bn1relu), H = g_h2, part = g_part2
__global__ __launch_bounds__(256, 2) void conv_kernel(
    const float* __restrict__ Xin, const int* __restrict__ IDX,
    const float* __restrict__ Wg, int which)
{
    const float* X   = which ? g_h1   : Xin;
    float*       H   = which ? g_h2   : g_h1;
    float*       part= which ? g_part2: g_part1;

    __shared__ __align__(16) float sW[1024];        // W[k]: [cin][cout]
    __shared__ __align__(16) float sX[8 * 1152];    // per-warp transposed x: [cin][36]
    __shared__ float red[2][8][32];

    const int tid  = threadIdx.x;
    const int warp = tid >> 5;
    const int lane = tid & 31;
    const int wbase = blockIdx.x * 256 + warp * 32;
    float* xw = sX + warp * 1152;

    unsigned long long acc[16];
#pragma unroll
    for (int i = 0; i < 16; i++) acc[i] = 0ULL;

    const int rowc = min(wbase + lane, N_ACT - 1);  // clamp keeps tail loads legal

#pragma unroll 1
    for (int k = 0; k < 8; k++) {
        __syncthreads();                             // prev k done with sW and xw
        // stage W[k] (coalesced, 4KB)
#pragma unroll
        for (int t = 0; t < 4; t++)
            sW[tid + 256 * t] = Wg[k * 1024 + tid + 256 * t];
        __syncthreads();

        // gather: each lane loads its own row (8x LDG.128), zero row for idx==N
        int j = IDX[(size_t)k * N_ACT + rowc];
        float4 v[8];
        if (j < N_ACT) {
            const float4* p = (const float4*)(X + (size_t)j * 32);
#pragma unroll
            for (int q = 0; q < 8; q++) v[q] = p[q];
        } else {
#pragma unroll
            for (int q = 0; q < 8; q++) v[q] = make_float4(0.f, 0.f, 0.f, 0.f);
        }

        // store transposed into shared: xw[cin*36 + r], lane writes column r=lane
        {
            float* col = xw + lane;
#pragma unroll
            for (int q = 0; q < 8; q++) {
                col[(4 * q + 0) * 36] = v[q].x;
                col[(4 * q + 1) * 36] = v[q].y;
                col[(4 * q + 2) * 36] = v[q].z;
                col[(4 * q + 3) * 36] = v[q].w;
            }
        }
        __syncwarp();

        // inner: per cin -> 8x LDS.128 broadcast (4 rows) + 16x fma.rn.f32x2
#pragma unroll
        for (int cin = 0; cin < 32; cin++) {
            unsigned long long ws = splat2(sW[cin * 32 + lane]);
            const ulonglong2* xp = (const ulonglong2*)(xw + cin * 36);
#pragma unroll
            for (int q = 0; q < 8; q++) {
                ulonglong2 t = xp[q];
                fma2(acc[2 * q],     t.x, ws);
                fma2(acc[2 * q + 1], t.y, ws);
            }
        }
    }

    // ---- BN stat partials (from registers) ----
    const int valid = N_ACT - wbase;   // may be <=0 for dead tail warps
    float s = 0.f, sq = 0.f;
#pragma unroll
    for (int m = 0; m < 16; m++) {
        float2 f = unpack2(acc[m]);
        if (2 * m     < valid) { s += f.x; sq += f.x * f.x; }
        if (2 * m + 1 < valid) { s += f.y; sq += f.y * f.y; }
    }
    red[0][warp][lane] = s;
    red[1][warp][lane] = sq;

    // ---- store H (coalesced: warp writes 128B per row) ----
#pragma unroll
    for (int m = 0; m < 16; m++) {
        float2 f = unpack2(acc[m]);
        int r0 = wbase + 2 * m;
        if (r0     < N_ACT) H[(size_t)r0 * 32 + lane]       = f.x;
        if (r0 + 1 < N_ACT) H[(size_t)(r0 + 1) * 32 + lane] = f.y;
    }

    __syncthreads();
    if (warp == 0) {
        float ts = 0.f, tq = 0.f;
#pragma unroll
        for (int w = 0; w < 8; w++) { ts += red[0][w][lane]; tq += red[1][w][lane]; }
        part[blockIdx.x * 64 + lane]      = ts;
        part[blockIdx.x * 64 + 32 + lane] = tq;
    }
}

// ---------------- reduce partials -> affine coefs a, c ----------------
__global__ void reduce_kernel(const float* __restrict__ gamma,
                              const float* __restrict__ beta, int which)
{
    const float* part = which ? g_part2 : g_part1;
    float*       coef = which ? g_coef2 : g_coef1;

    const int c = threadIdx.x & 31;
    const int s = threadIdx.x >> 5;   // 32 slices, 1024 threads
    float s1 = 0.f, s2 = 0.f;
    for (int b = s; b < NB_CONV; b += 32) {
        s1 += part[b * 64 + c];
        s2 += part[b * 64 + 32 + c];
    }
    __shared__ float sh1[32][33], sh2[32][33];
    sh1[c][s] = s1;
    sh2[c][s] = s2;
    __syncthreads();
    if (s == 0) {
        float sum = 0.f, sq = 0.f;
#pragma unroll
        for (int i = 0; i < 32; i++) { sum += sh1[c][i]; sq += sh2[c][i]; }
        float mean = sum / (float)N_ACT;
        float var  = fmaxf(sq / (float)N_ACT - mean * mean, 0.f);
        float a    = gamma[c] * rsqrtf(var + BN_EPS);
        coef[c]      = a;
        coef[32 + c] = beta[c] - mean * a;
    }
}

// ---------------- bn1 + relu, in place on g_h1 ----------------
__global__ void bnrelu_kernel()
{
    int i4 = blockIdx.x * 256 + threadIdx.x;     // exactly N*8 float4s
    int cb = i4 & 7;
    float4 a = ((const float4*)g_coef1)[cb];
    float4 c = ((const float4*)g_coef1)[8 + cb];
    float4 v = ((const float4*)g_h1)[i4];
    v.x = fmaxf(fmaf(v.x, a.x, c.x), 0.f);
    v.y = fmaxf(fmaf(v.y, a.y, c.y), 0.f);
    v.z = fmaxf(fmaf(v.z, a.z, c.z), 0.f);
    v.w = fmaxf(fmaf(v.w, a.w, c.w), 0.f);
    ((float4*)g_h1)[i4] = v;
}

// ---------------- bn2 + residual add -> out ----------------
__global__ void final_kernel(const float* __restrict__ X, float* __restrict__ O)
{
    int i4 = blockIdx.x * 256 + threadIdx.x;
    int cb = i4 & 7;
    float4 a = ((const float4*)g_coef2)[cb];
    float4 c = ((const float4*)g_coef2)[8 + cb];
    float4 v = ((const float4*)g_h2)[i4];
    float4 x = ((const float4*)X)[i4];
    float4 o;
    o.x = fmaf(v.x, a.x, c.x) + x.x;
    o.y = fmaf(v.y, a.y, c.y) + x.y;
    o.z = fmaf(v.z, a.z, c.z) + x.z;
    o.w = fmaf(v.w, a.w, c.w) + x.w;
    ((float4*)O)[i4] = o;
}

extern "C" void kernel_launch(void* const* d_in, const int* in_sizes, int n_in,
                              void* d_out, int out_size)
{
    const float* x   = (const float*)d_in[0];
    const int*   idx = (const int*)  d_in[1];
    const float* W1  = (const float*)d_in[2];
    const float* g1  = (const float*)d_in[3];
    const float* b1  = (const float*)d_in[4];
    const float* W2  = (const float*)d_in[5];
    const float* g2  = (const float*)d_in[6];
    const float* b2  = (const float*)d_in[7];
    float* out = (float*)d_out;

    conv_kernel  <<<NB_CONV, 256>>>(x, idx, W1, 0);   // h1 = conv1(x), partials1
    reduce_kernel<<<1, 1024>>>(g1, b1, 0);            // coef1
    bnrelu_kernel<<<NB_ELT, 256>>>();                 // h1 = relu(bn1(h1)) in place
    conv_kernel  <<<NB_CONV, 256>>>(x, idx, W2, 1);   // h2 = conv2(h1), partials2
    reduce_kernel<<<1, 1024>>>(g2, b2, 1);            // coef2
    final_kernel <<<NB_ELT, 256>>>(x, out);           // out = bn2(h2) + x
}

// round 2
// speedup vs baseline: 1.1545x; 1.1545x over previous
#include <cuda_runtime.h>
#include <cstdint>

#define N_ACT   1500000
#define NB_CONV ((N_ACT + 255) / 256)        // 5860 blocks, 256 rows each
#define NB_ELT  ((N_ACT * 8) / 256)          // N*32 floats / 4 per thread / 256
#define BN_EPS  1e-5f

// ---------------- scratch (no allocations allowed) ----------------
__device__ float g_h1[(size_t)N_ACT * 32];     // conv1 raw output
__device__ float g_h2[(size_t)N_ACT * 32];     // conv2 raw output
__device__ float g_part1[NB_CONV * 64];        // per-block [sum(32), sumsq(32)]
__device__ float g_part2[NB_CONV * 64];
__device__ float g_coef1[64];                  // [a(32), c(32)] : y = a*h + c
__device__ float g_coef2[64];

// ---------------- f32x2 helpers (Blackwell packed fp32) ----------------
__device__ __forceinline__ unsigned long long splat2(float w) {
    unsigned long long r;
    asm("mov.b64 %0, {%1, %1};" : "=l"(r) : "f"(w));
    return r;
}
__device__ __forceinline__ float2 unpack2(unsigned long long v) {
    float2 f;
    asm("mov.b64 {%0, %1}, %2;" : "=f"(f.x), "=f"(f.y) : "l"(v));
    return f;
}
__device__ __forceinline__ void fma2(unsigned long long& acc,
                                     unsigned long long x,
                                     unsigned long long w) {
    asm("fma.rn.f32x2 %0, %1, %2, %0;" : "+l"(acc) : "l"(x), "l"(w));
}

// ---------------- conv: H[i] = sum_k gather(X, idx[k]) @ W[k] ----------------
// Warp tile: 32 rows x 32 cout. lane = cout in compute; lane = cin in gather.
// WHICH==0: X = Xin raw,              H = g_h1, part = g_part1
// WHICH==1: X = bn1relu(g_h1) inline, H = g_h2, part = g_part2
template<int WHICH>
__global__ __launch_bounds__(256, 2) void conv_kernel(
    const float* __restrict__ Xin, const int* __restrict__ IDX,
    const float* __restrict__ Wg)
{
    const float* X    = WHICH ? g_h1    : Xin;
    float*       H    = WHICH ? g_h2    : g_h1;
    float*       part = WHICH ? g_part2 : g_part1;

    // per-warp transposed tile: [cin][row], stride 36 floats (144B, 16B aligned)
    __shared__ __align__(16) float sX[8 * 1152];
    __shared__ float red[2][8][32];

    const int tid   = threadIdx.x;
    const int warp  = tid >> 5;
    const int lane  = tid & 31;
    const int wbase = blockIdx.x * 256 + warp * 32;
    float* xw = sX + warp * 1152;

    // bn1+relu coefs for the fused gather transform (lane == channel)
    float a_bn = 0.f, c_bn = 0.f;
    if (WHICH) { a_bn = g_coef1[lane]; c_bn = g_coef1[32 + lane]; }

    unsigned long long acc[16];
#pragma unroll
    for (int i = 0; i < 16; i++) acc[i] = 0ULL;

    const int rowc = min(wbase + lane, N_ACT - 1);  // clamp keeps tail legal

#pragma unroll 1
    for (int k = 0; k < 8; k++) {
        // ---- cooperative coalesced gather: row r -> lanes read 128B together
        const int myj = IDX[(size_t)k * N_ACT + rowc];
        float vals[32];
#pragma unroll
        for (int r = 0; r < 32; r++) {
            int j = __shfl_sync(0xffffffffu, myj, r);   // warp-uniform
            float t = 0.f;
            if (j < N_ACT) {
                t = X[(size_t)j * 32 + lane];
                if (WHICH) t = fmaxf(fmaf(t, a_bn, c_bn), 0.f);
            }
            vals[r] = t;
        }
        __syncwarp();   // compute of previous k done reading xw
        // lane(=cin) writes its column, contiguous rows -> STS.128, conflict-free
#pragma unroll
        for (int q = 0; q < 8; q++) {
            float4 v = make_float4(vals[4 * q], vals[4 * q + 1],
                                   vals[4 * q + 2], vals[4 * q + 3]);
            *(float4*)(xw + lane * 36 + 4 * q) = v;
        }
        __syncwarp();

        // ---- compute: per cin -> 1 LDG.32 (W, L1-hot) + 8 LDS.128 bcast + 16 fma2
#pragma unroll
        for (int cin = 0; cin < 32; cin++) {
            unsigned long long ws = splat2(Wg[k * 1024 + cin * 32 + lane]);
            const ulonglong2* xp = (const ulonglong2*)(xw + cin * 36);
#pragma unroll
            for (int q = 0; q < 8; q++) {
                ulonglong2 t = xp[q];
                fma2(acc[2 * q],     t.x, ws);
                fma2(acc[2 * q + 1], t.y, ws);
            }
        }
    }

    // ---- BN stat partials (from registers) ----
    const int valid = N_ACT - wbase;   // may be <=0 for dead tail warps
    float s = 0.f, sq = 0.f;
#pragma unroll
    for (int m = 0; m < 16; m++) {
        float2 f = unpack2(acc[m]);
        if (2 * m     < valid) { s += f.x; sq += f.x * f.x; }
        if (2 * m + 1 < valid) { s += f.y; sq += f.y * f.y; }
    }
    red[0][warp][lane] = s;
    red[1][warp][lane] = sq;

    // ---- store H (coalesced: warp writes 128B per row) ----
#pragma unroll
    for (int m = 0; m < 16; m++) {
        float2 f = unpack2(acc[m]);
        int r0 = wbase + 2 * m;
        if (r0     < N_ACT) H[(size_t)r0 * 32 + lane]       = f.x;
        if (r0 + 1 < N_ACT) H[(size_t)(r0 + 1) * 32 + lane] = f.y;
    }

    __syncthreads();
    if (warp == 0) {
        float ts = 0.f, tq = 0.f;
#pragma unroll
        for (int w = 0; w < 8; w++) { ts += red[0][w][lane]; tq += red[1][w][lane]; }
        part[blockIdx.x * 64 + lane]      = ts;
        part[blockIdx.x * 64 + 32 + lane] = tq;
    }
}

// ---------------- reduce partials -> affine coefs a, c ----------------
__global__ void reduce_kernel(const float* __restrict__ gamma,
                              const float* __restrict__ beta, int which)
{
    const float* part = which ? g_part2 : g_part1;
    float*       coef = which ? g_coef2 : g_coef1;

    const int c = threadIdx.x & 31;
    const int s = threadIdx.x >> 5;   // 32 slices, 1024 threads
    float s1 = 0.f, s2 = 0.f;
    for (int b = s; b < NB_CONV; b += 32) {
        s1 += part[b * 64 + c];
        s2 += part[b * 64 + 32 + c];
    }
    __shared__ float sh1[32][33], sh2[32][33];
    sh1[c][s] = s1;
    sh2[c][s] = s2;
    __syncthreads();
    if (s == 0) {
        float sum = 0.f, sq = 0.f;
#pragma unroll
        for (int i = 0; i < 32; i++) { sum += sh1[c][i]; sq += sh2[c][i]; }
        float mean = sum / (float)N_ACT;
        float var  = fmaxf(sq / (float)N_ACT - mean * mean, 0.f);
        float a    = gamma[c] * rsqrtf(var + BN_EPS);
        coef[c]      = a;
        coef[32 + c] = beta[c] - mean * a;
    }
}

// ---------------- bn2 + residual add -> out ----------------
__global__ void final_kernel(const float* __restrict__ X, float* __restrict__ O)
{
    int i4 = blockIdx.x * 256 + threadIdx.x;
    int cb = i4 & 7;
    float4 a = ((const float4*)g_coef2)[cb];
    float4 c = ((const float4*)g_coef2)[8 + cb];
    float4 v = ((const float4*)g_h2)[i4];
    float4 x = ((const float4*)X)[i4];
    float4 o;
    o.x = fmaf(v.x, a.x, c.x) + x.x;
    o.y = fmaf(v.y, a.y, c.y) + x.y;
    o.z = fmaf(v.z, a.z, c.z) + x.z;
    o.w = fmaf(v.w, a.w, c.w) + x.w;
    ((float4*)O)[i4] = o;
}

extern "C" void kernel_launch(void* const* d_in, const int* in_sizes, int n_in,
                              void* d_out, int out_size)
{
    const float* x   = (const float*)d_in[0];
    const int*   idx = (const int*)  d_in[1];
    const float* W1  = (const float*)d_in[2];
    const float* g1  = (const float*)d_in[3];
    const float* b1  = (const float*)d_in[4];
    const float* W2  = (const float*)d_in[5];
    const float* g2  = (const float*)d_in[6];
    const float* b2  = (const float*)d_in[7];
    float* out = (float*)d_out;

    conv_kernel<0><<<NB_CONV, 256>>>(x, idx, W1);     // h1 = conv1(x), partials1
    reduce_kernel <<<1, 1024>>>(g1, b1, 0);           // coef1
    conv_kernel<1><<<NB_CONV, 256>>>(x, idx, W2);     // h2 = conv2(bn1relu(h1)), partials2
    reduce_kernel <<<1, 1024>>>(g2, b2, 1);           // coef2
    final_kernel  <<<NB_ELT, 256>>>(x, out);          // out = bn2(h2) + x
}

// round 3
// speedup vs baseline: 1.2892x; 1.1167x over previous
#include <cuda_runtime.h>
#include <cstdint>

#define N_ACT   1500000
#define ROWS_PB 128                            // 8 warps x 16 rows
#define NB_CONV ((N_ACT + ROWS_PB - 1) / ROWS_PB)   // 11719 blocks
#define NB_ELT  ((N_ACT * 8) / 256)            // N*32 floats / 4 per thread / 256
#define BN_EPS  1e-5f
#define XS      20                             // smem stride (floats) per cin

// ---------------- scratch (no allocations allowed) ----------------
__device__ float g_h1[(size_t)N_ACT * 32];     // conv1 raw output
__device__ float g_h2[(size_t)N_ACT * 32];     // conv2 raw output
__device__ float g_part1[NB_CONV * 64];        // per-block [sum(32), sumsq(32)]
__device__ float g_part2[NB_CONV * 64];
__device__ float g_coef1[64];                  // [a(32), c(32)] : y = a*h + c
__device__ float g_coef2[64];

// ---------------- f32x2 helpers (Blackwell packed fp32) ----------------
__device__ __forceinline__ unsigned long long splat2(float w) {
    unsigned long long r;
    asm("mov.b64 %0, {%1, %1};" : "=l"(r) : "f"(w));
    return r;
}
__device__ __forceinline__ float2 unpack2(unsigned long long v) {
    float2 f;
    asm("mov.b64 {%0, %1}, %2;" : "=f"(f.x), "=f"(f.y) : "l"(v));
    return f;
}
__device__ __forceinline__ void fma2(unsigned long long& acc,
                                     unsigned long long x,
                                     unsigned long long w) {
    asm("fma.rn.f32x2 %0, %1, %2, %0;" : "+l"(acc) : "l"(x), "l"(w));
}

// ---------------- conv: H[i] = sum_k gather(X, idx[k]) @ W[k] ----------------
// Warp tile: 16 rows x 32 cout. lane = cout in compute; lane = cin in gather.
// WHICH==0: X = Xin raw,              H = g_h1, part = g_part1
// WHICH==1: X = bn1relu(g_h1) inline, H = g_h2, part = g_part2
template<int WHICH>
__global__ __launch_bounds__(256, 4) void conv_kernel(
    const float* __restrict__ Xin, const int* __restrict__ IDX,
    const float* __restrict__ Wg)
{
    const float* X    = WHICH ? g_h1    : Xin;
    float*       H    = WHICH ? g_h2    : g_h1;
    float*       part = WHICH ? g_part2 : g_part1;

    // per-warp transposed tile: [cin][row], stride XS=20 floats (80B, 16B aligned)
    __shared__ __align__(16) float sX[8 * 32 * XS];
    __shared__ float red[2][8][32];

    const int tid   = threadIdx.x;
    const int warp  = tid >> 5;
    const int lane  = tid & 31;
    const int wbase = blockIdx.x * ROWS_PB + warp * 16;
    float* xw = sX + warp * 32 * XS;

    // bn1+relu coefs for the fused gather transform (lane == channel)
    float a_bn = 0.f, c_bn = 0.f;
    if (WHICH) { a_bn = g_coef1[lane]; c_bn = g_coef1[32 + lane]; }

    unsigned long long acc[8];
#pragma unroll
    for (int i = 0; i < 8; i++) acc[i] = 0ULL;

    // idx row for this lane (lanes 16-31 duplicate 0-15); clamp keeps tail legal
    const int rowc = min(wbase + (lane & 15), N_ACT - 1);

#pragma unroll 1
    for (int k = 0; k < 8; k++) {
        // ---- cooperative coalesced gather: row r -> all lanes read 128B together
        const int myj = IDX[(size_t)k * N_ACT + rowc];
        float vals[16];
#pragma unroll
        for (int r = 0; r < 16; r++) {
            int j = __shfl_sync(0xffffffffu, myj, r);   // warp-uniform
            float t = 0.f;
            if (j < N_ACT) {
                t = X[(size_t)j * 32 + lane];
                if (WHICH) t = fmaxf(fmaf(t, a_bn, c_bn), 0.f);
            }
            vals[r] = t;
        }
        __syncwarp();   // compute of previous k done reading xw
        // lane(=cin) writes its column: 4x STS.128, conflict-free (banks 0..31 once)
#pragma unroll
        for (int q = 0; q < 4; q++) {
            float4 v = make_float4(vals[4 * q], vals[4 * q + 1],
                                   vals[4 * q + 2], vals[4 * q + 3]);
            *(float4*)(xw + lane * XS + 4 * q) = v;
        }
        __syncwarp();

        // ---- compute: per cin -> 1 LDG.32 (W, L1-hot) + 4 LDS.128 bcast + 8 fma2
#pragma unroll
        for (int cin = 0; cin < 32; cin++) {
            unsigned long long ws = splat2(Wg[k * 1024 + cin * 32 + lane]);
            const ulonglong2* xp = (const ulonglong2*)(xw + cin * XS);
#pragma unroll
            for (int q = 0; q < 4; q++) {
                ulonglong2 t = xp[q];
                fma2(acc[2 * q],     t.x, ws);
                fma2(acc[2 * q + 1], t.y, ws);
            }
        }
    }

    // ---- BN stat partials (from registers) ----
    const int valid = N_ACT - wbase;   // may be <=0 for dead tail warps
    float s = 0.f, sq = 0.f;
#pragma unroll
    for (int m = 0; m < 8; m++) {
        float2 f = unpack2(acc[m]);
        if (2 * m     < valid) { s += f.x; sq += f.x * f.x; }
        if (2 * m + 1 < valid) { s += f.y; sq += f.y * f.y; }
    }
    red[0][warp][lane] = s;
    red[1][warp][lane] = sq;

    // ---- store H (coalesced: warp writes 128B per row) ----
#pragma unroll
    for (int m = 0; m < 8; m++) {
        float2 f = unpack2(acc[m]);
        int r0 = wbase + 2 * m;
        if (r0     < N_ACT) H[(size_t)r0 * 32 + lane]       = f.x;
        if (r0 + 1 < N_ACT) H[(size_t)(r0 + 1) * 32 + lane] = f.y;
    }

    __syncthreads();
    if (warp == 0) {
        float ts = 0.f, tq = 0.f;
#pragma unroll
        for (int w = 0; w < 8; w++) { ts += red[0][w][lane]; tq += red[1][w][lane]; }
        part[blockIdx.x * 64 + lane]      = ts;
        part[blockIdx.x * 64 + 32 + lane] = tq;
    }
}

// ---------------- reduce partials -> affine coefs a, c ----------------
__global__ void reduce_kernel(const float* __restrict__ gamma,
                              const float* __restrict__ beta, int which)
{
    const float* part = which ? g_part2 : g_part1;
    float*       coef = which ? g_coef2 : g_coef1;

    const int c = threadIdx.x & 31;
    const int s = threadIdx.x >> 5;   // 32 slices, 1024 threads
    float s1 = 0.f, s2 = 0.f;
    for (int b = s; b < NB_CONV; b += 32) {
        s1 += part[b * 64 + c];
        s2 += part[b * 64 + 32 + c];
    }
    __shared__ float sh1[32][33], sh2[32][33];
    sh1[c][s] = s1;
    sh2[c][s] = s2;
    __syncthreads();
    if (s == 0) {
        float sum = 0.f, sq = 0.f;
#pragma unroll
        for (int i = 0; i < 32; i++) { sum += sh1[c][i]; sq += sh2[c][i]; }
        float mean = sum / (float)N_ACT;
        float var  = fmaxf(sq / (float)N_ACT - mean * mean, 0.f);
        float a    = gamma[c] * rsqrtf(var + BN_EPS);
        coef[c]      = a;
        coef[32 + c] = beta[c] - mean * a;
    }
}

// ---------------- bn2 + residual add -> out ----------------
__global__ void final_kernel(const float* __restrict__ X, float* __restrict__ O)
{
    int i4 = blockIdx.x * 256 + threadIdx.x;
    int cb = i4 & 7;
    float4 a = ((const float4*)g_coef2)[cb];
    float4 c = ((const float4*)g_coef2)[8 + cb];
    float4 v = ((const float4*)g_h2)[i4];
    float4 x = ((const float4*)X)[i4];
    float4 o;
    o.x = fmaf(v.x, a.x, c.x) + x.x;
    o.y = fmaf(v.y, a.y, c.y) + x.y;
    o.z = fmaf(v.z, a.z, c.z) + x.z;
    o.w = fmaf(v.w, a.w, c.w) + x.w;
    ((float4*)O)[i4] = o;
}

extern "C" void kernel_launch(void* const* d_in, const int* in_sizes, int n_in,
                              void* d_out, int out_size)
{
    const float* x   = (const float*)d_in[0];
    const int*   idx = (const int*)  d_in[1];
    const float* W1  = (const float*)d_in[2];
    const float* g1  = (const float*)d_in[3];
    const float* b1  = (const float*)d_in[4];
    const float* W2  = (const float*)d_in[5];
    const float* g2  = (const float*)d_in[6];
    const float* b2  = (const float*)d_in[7];
    float* out = (float*)d_out;

    conv_kernel<0><<<NB_CONV, 256>>>(x, idx, W1);     // h1 = conv1(x), partials1
    reduce_kernel <<<1, 1024>>>(g1, b1, 0);           // coef1
    conv_kernel<1><<<NB_CONV, 256>>>(x, idx, W2);     // h2 = conv2(bn1relu(h1)), partials2
    reduce_kernel <<<1, 1024>>>(g2, b2, 1);           // coef2
    final_kernel  <<<NB_ELT, 256>>>(x, out);          // out = bn2(h2) + x
}